// round 15
// baseline (speedup 1.0000x reference)
#include <cuda_runtime.h>
#include <cuda_bf16.h>
#include <cstdint>

// ---------------------------------------------------------------------------
// DownSample: FPS(64->32) + gathers + conv(1x3,s=2,p=1) 128->256 as a
// bf16-split mma.sync GEMM (HMMA) + BatchNorm(batch stats) + tanh-GELU.
//
// conv as GEMM: D[o, n] = sum_k W[o,k] X[n,k],  k = tap*128 + i  (K=384)
// bf16 3-term split: W = Wh + Wl, X = Xh + Xl;  D ~= Wh*Xh + Wh*Xl + Wl*Xh.
//
// Output layout in d_out (float32):
//   [0        , 524288)    sparse_out      [64,256,32]
//   [524288   , 17301504)  dense_out       [64,256,1024]
//   [17301504 , 17367040)  stk_coor_sampled[64,32,32]
// ---------------------------------------------------------------------------

#define N_STK    64
#define N_HALF   32
#define N_PNT    64
#define COOR_EMB 32
#define BS       64
#define C_IN     128
#define C_OUT    256
#define SP_EMB   256
#define NBLK     1024        // conv CTAs = 64 b x 16 stroke-pairs
#define KSTEPS   24          // K=384 / 16

// dynamic smem (bytes): B data 96KB, A weights 4x16KB ring
#define SB_B     0           // [h][384 k-rows][128 B] xor-swizzled
#define SB_A     98304       // 4 bufs x 16384
#define SMEM_TOT 163840

__device__ __align__(16) int            g_fps_idx[BS * N_HALF];
__device__ __align__(16) unsigned short g_wA[KSTEPS * 8192];           // ldmatrix-tiled bf16 weights
__device__ __align__(16) float          g_y[(size_t)BS * C_OUT * 1024]; // conv out (64 MB)
__device__ __align__(16) float2         g_ps[NBLK * C_OUT];             // per-CTA (sum, sumsq)
__device__ __align__(16) float          g_scale[C_OUT];
__device__ __align__(16) float          g_shift[C_OUT];

// ---------------- PTX helpers (plain compute_103-legal) ----------
__device__ __forceinline__ uint32_t smem_u32(const void* p) {
    uint32_t a;
    asm("{ .reg .u64 t; cvta.to.shared.u64 t, %1; cvt.u32.u64 %0, t; }" : "=r"(a) : "l"(p));
    return a;
}
#define CP_ASYNC16(dst, src) \
    asm volatile("cp.async.ca.shared.global [%0], [%1], 16;" :: "r"(dst), "l"(src))
#define CP_COMMIT() asm volatile("cp.async.commit_group;" ::: "memory")
#define CP_WAIT2()  asm volatile("cp.async.wait_group 2;" ::: "memory")
#define LDX4(r, a) \
    asm volatile("ldmatrix.sync.aligned.m8n8.x4.shared.b16 {%0,%1,%2,%3}, [%4];" \
        : "=r"((r)[0]), "=r"((r)[1]), "=r"((r)[2]), "=r"((r)[3]) : "r"(a))
#define LDX4T(r, a) \
    asm volatile("ldmatrix.sync.aligned.m8n8.x4.trans.shared.b16 {%0,%1,%2,%3}, [%4];" \
        : "=r"((r)[0]), "=r"((r)[1]), "=r"((r)[2]), "=r"((r)[3]) : "r"(a))
#define MMA(d, a, b0, b1) \
    asm volatile("mma.sync.aligned.m16n8k16.row.col.f32.bf16.bf16.f32 " \
        "{%0,%1,%2,%3},{%4,%5,%6,%7},{%8,%9},{%0,%1,%2,%3};" \
        : "+f"((d)[0]), "+f"((d)[1]), "+f"((d)[2]), "+f"((d)[3]) \
        : "r"((a)[0]), "r"((a)[1]), "r"((a)[2]), "r"((a)[3]), "r"(b0), "r"(b1))

__device__ __forceinline__ unsigned short f2bh(float x) {
    __nv_bfloat16 h = __float2bfloat16_rn(x);
    return __bfloat16_as_ushort(h);
}
__device__ __forceinline__ float bh2f(unsigned short u) {
    return __bfloat162float(__ushort_as_bfloat16(u));
}

// ---------------- K1: farthest point sampling -------------------
__global__ void fps_kernel(const float* __restrict__ coor, float* __restrict__ coor_out) {
    int b = blockIdx.x;
    int n = threadIdx.x;

    float p[COOR_EMB];
    const float4* src = (const float4*)(coor + ((size_t)b * N_STK + n) * COOR_EMB);
#pragma unroll
    for (int q = 0; q < COOR_EMB / 4; q++) {
        float4 v = src[q];
        p[4 * q + 0] = v.x; p[4 * q + 1] = v.y; p[4 * q + 2] = v.z; p[4 * q + 3] = v.w;
    }

    __shared__ __align__(16) float cen[COOR_EMB];
    __shared__ float sd[N_STK];
    __shared__ int   si[N_STK];

    float dist = 1e10f;
    int farthest = 0;

    for (int it = 0; it < N_HALF; it++) {
        if (n == 0) g_fps_idx[b * N_HALF + it] = farthest;
        if (n == farthest) {
            float* co = coor_out + ((size_t)b * N_HALF + it) * COOR_EMB;
#pragma unroll
            for (int c = 0; c < COOR_EMB; c++) { cen[c] = p[c]; co[c] = p[c]; }
        }
        __syncthreads();

        float d = 0.f;
#pragma unroll
        for (int c = 0; c < COOR_EMB; c++) {
            float df = p[c] - cen[c];
            d = fmaf(df, df, d);
        }
        dist = fminf(dist, d);

        sd[n] = dist; si[n] = n;
        __syncthreads();
#pragma unroll
        for (int st = 32; st > 0; st >>= 1) {
            if (n < st) {
                float dv = sd[n + st]; int iv = si[n + st];
                if (dv > sd[n] || (dv == sd[n] && iv < si[n])) { sd[n] = dv; si[n] = iv; }
            }
            __syncthreads();
        }
        farthest = si[0];
        __syncthreads();
    }
}

// ---------------- K2a: sparse gather ----------------------------
__global__ void gather_sparse(const float* __restrict__ sp, float* __restrict__ out) {
    int gid = blockIdx.x * blockDim.x + threadIdx.x;
    if (gid < BS * SP_EMB * N_HALF) {
        int s = gid & 31;
        int e = (gid >> 5) & 255;
        int b = gid >> 13;
        int sid = g_fps_idx[b * N_HALF + s];
        out[gid] = sp[((size_t)b * SP_EMB + e) * N_STK + sid];
    }
}

// ---------------- K2b: ldmatrix-tiled bf16 weight split ---------
// elem idx = ((((ks*2 + h)*16 + MT)*4 + mat)*8 + row)*8 + col
//   m = MT*16 + (mat&1)*8 + row ; k = ks*16 + (mat>>1)*8 + col
//   tap = k>>7 ; i = k&127 ; h=0 -> bf16 hi, h=1 -> residual lo
__global__ void wsplit(const float* __restrict__ w) {
    int idx = blockIdx.x * blockDim.x + threadIdx.x;
    if (idx < KSTEPS * 8192) {
        int col = idx & 7;
        int row = (idx >> 3) & 7;
        int mat = (idx >> 6) & 3;
        int MT  = (idx >> 8) & 15;
        int h   = (idx >> 12) & 1;
        int ks  = idx >> 13;
        int m = MT * 16 + (mat & 1) * 8 + row;
        int k = ks * 16 + (mat >> 1) * 8 + col;
        int tap = k >> 7, i = k & 127;
        float wv = w[m * (C_IN * 3) + i * 3 + tap];
        unsigned short wh = f2bh(wv);
        g_wA[idx] = h ? f2bh(wv - bh2f(wh)) : wh;
    }
}

// ---------------- K3: conv GEMM via mma.sync bf16 ----------------
// CTA = (b, stroke-pair): M=256 (16 warps x m16), N=64, K=384.
// A streamed PER-WARP through a 4-stage cp.async ring (warp-disjoint slices
// that match the warp's own reads; no __syncthreads in the mainloop).
__global__ __launch_bounds__(512, 1)
void conv_mma_kernel(const float* __restrict__ dense, const float* __restrict__ bias) {
    extern __shared__ __align__(16) unsigned char dsm[];
    int tid = threadIdx.x, lane = tid & 31, w = tid >> 5;   // w = 0..15
    int cta = blockIdx.x;
    int b = cta >> 4, sp = cta & 15;

    uint32_t sbA = smem_u32(dsm + SB_A);
    uint32_t sbB = smem_u32(dsm + SB_B);
    const char* gA = (const char*)g_wA;

    // warp w's A slice in each 16KB kstep block: hi [w*512, +512), lo at +8192.
    uint32_t sliceH = (uint32_t)w * 512 + (uint32_t)lane * 16;
    size_t   srcH   = (size_t)w * 512 + (size_t)lane * 16;

    // prologue: each warp streams its slices of ksteps 0..2 (3 groups)
#pragma unroll
    for (int pk = 0; pk < 3; pk++) {
        uint32_t dst = sbA + (uint32_t)pk * 16384 + sliceH;
        const char* src = gA + (size_t)pk * 16384 + srcH;
        CP_ASYNC16(dst, src);
        CP_ASYNC16(dst + 8192, src + 8192);
        CP_COMMIT();
    }

    // ---- build B (data) rows: k = tap*128 + i, 128 B/row, xor swizzle ----
    // 512 threads: 4 per channel — (stroke g, q-half hq), 8 q's each.
    {
        int i = tid & 127;
        int quarter = tid >> 7;           // 0..3
        int g = quarter >> 1, hq = quarter & 1;
        int s = sp * 2 + g;
        int sid = g_fps_idx[b * N_HALF + s];
        const float* basep = dense + ((size_t)b * C_IN + i) * (N_STK * N_PNT)
                             + (size_t)sid * N_PNT;
        const float4* r4 = (const float4*)basep;
        char* Bh = (char*)dsm + SB_B;
        char* Bl = (char*)dsm + SB_B + 49152;
        uint32_t kS = i, kU = 128 + i, kV = 256 + i;
        uint32_t swS = (kS & 7) << 4, swU = (kU & 7) << 4, swV = (kV & 7) << 4;
        uint32_t ph = 0, pl = 0;          // prev v (left pad = 0)
        if (hq) {                          // prev v for q=8 is d[31]
            float pv = basep[31];
            unsigned short pvh = f2bh(pv);
            ph = pvh; pl = f2bh(pv - bh2f(pvh));
        }
#pragma unroll
        for (int qq = 0; qq < 8; qq++) {
            int q = hq * 8 + qq;
            float4 x = r4[q];
            unsigned short u0h = f2bh(x.x), v0h = f2bh(x.y);
            unsigned short u1h = f2bh(x.z), v1h = f2bh(x.w);
            unsigned short u0l = f2bh(x.x - bh2f(u0h));
            unsigned short v0l = f2bh(x.y - bh2f(v0h));
            unsigned short u1l = f2bh(x.z - bh2f(u1h));
            unsigned short v1l = f2bh(x.w - bh2f(v1h));
            uint32_t n2 = (uint32_t)(g * 32 + 2 * q) * 2;   // byte col
            *(uint32_t*)(Bh + kU * 128 + (n2 ^ swU)) = (uint32_t)u0h | ((uint32_t)u1h << 16);
            *(uint32_t*)(Bl + kU * 128 + (n2 ^ swU)) = (uint32_t)u0l | ((uint32_t)u1l << 16);
            *(uint32_t*)(Bh + kV * 128 + (n2 ^ swV)) = (uint32_t)v0h | ((uint32_t)v1h << 16);
            *(uint32_t*)(Bl + kV * 128 + (n2 ^ swV)) = (uint32_t)v0l | ((uint32_t)v1l << 16);
            *(uint32_t*)(Bh + kS * 128 + (n2 ^ swS)) = ph | ((uint32_t)v0h << 16);
            *(uint32_t*)(Bl + kS * 128 + (n2 ^ swS)) = pl | ((uint32_t)v0l << 16);
            ph = v1h; pl = v1l;
        }
    }
    __syncthreads();   // B visible; no more block syncs until epilogue

    float acc[8][4];
#pragma unroll
    for (int nt = 0; nt < 8; nt++)
#pragma unroll
        for (int e = 0; e < 4; e++) acc[nt][e] = 0.f;

    int j = lane >> 3;                       // matrix index 0..3
    int krow = (j & 1) * 8 + (lane & 7);     // k within kstep
    int ncol = (j >> 1) * 8;                 // n offset

    for (int ks = 0; ks < KSTEPS; ks++) {
        int buf = ks & 3;
        CP_WAIT2();          // this thread's group ks retired (pending kept at 3)
        __syncwarp();        // warp-local visibility of the warp's own slice

        // prefetch warp slice of kstep ks+3 into buf (ks+3)&3 = (ks-1)&3,
        // which THIS warp finished reading last iteration. commit always.
        if (ks + 3 < KSTEPS) {
            uint32_t dst = sbA + (uint32_t)((ks + 3) & 3) * 16384 + sliceH;
            const char* src = gA + (size_t)(ks + 3) * 16384 + srcH;
            CP_ASYNC16(dst, src);
            CP_ASYNC16(dst + 8192, src + 8192);
        }
        CP_COMMIT();

        // A fragments (hi+lo) for this warp's m16 tile
        uint32_t aB = sbA + (uint32_t)buf * 16384 + (uint32_t)w * 512
                      + (uint32_t)(lane >> 3) * 128 + (uint32_t)(lane & 7) * 16;
        uint32_t Ah[4], Al[4];
        LDX4(Ah, aB);
        LDX4(Al, aB + 8192);

        int kk = ks * 16 + krow;
        uint32_t rowb = (uint32_t)kk * 128;
        uint32_t swz = (uint32_t)(kk & 7) << 4;

        uint32_t Bf[4][4];
        // ---- X hi: Wh*Xh + Wl*Xh ----
#pragma unroll
        for (int np = 0; np < 4; np++) {
            uint32_t nb = (uint32_t)((np * 16 + ncol) * 2);
            LDX4T(Bf[np], sbB + rowb + (nb ^ swz));
        }
#pragma unroll
        for (int np = 0; np < 4; np++) {
            MMA(acc[np * 2],     Ah, Bf[np][0], Bf[np][1]);
            MMA(acc[np * 2 + 1], Ah, Bf[np][2], Bf[np][3]);
            MMA(acc[np * 2],     Al, Bf[np][0], Bf[np][1]);
            MMA(acc[np * 2 + 1], Al, Bf[np][2], Bf[np][3]);
        }
        // ---- X lo: Wh*Xl ----
#pragma unroll
        for (int np = 0; np < 4; np++) {
            uint32_t nb = (uint32_t)((np * 16 + ncol) * 2);
            LDX4T(Bf[np], sbB + 49152 + rowb + (nb ^ swz));
        }
#pragma unroll
        for (int np = 0; np < 4; np++) {
            MMA(acc[np * 2],     Ah, Bf[np][0], Bf[np][1]);
            MMA(acc[np * 2 + 1], Ah, Bf[np][2], Bf[np][3]);
        }
    }
    __syncthreads();

    // ---- epilogue: stage D in smem, then bias + BN partials + store ----
    float* sy = (float*)dsm;    // 256 rows x stride 66 = 67.6 KB
    int r = lane >> 2, c2 = (lane & 3) * 2;
    {
        int m = w * 16 + r;
#pragma unroll
        for (int nt = 0; nt < 8; nt++) {
            int n = nt * 8 + c2;
            *(float2*)(sy + m * 66 + n)       = make_float2(acc[nt][0], acc[nt][1]);
            *(float2*)(sy + (m + 8) * 66 + n) = make_float2(acc[nt][2], acc[nt][3]);
        }
    }
    __syncthreads();

    {
        int o = tid >> 1;          // 0..255
        int half = tid & 1;
        float bv = bias[o];
        float S = 0.f, Q = 0.f;
        float* row = sy + o * 66 + half * 32;
        float* dst = g_y + ((size_t)b * C_OUT + o) * 1024 + sp * 64 + half * 32;
#pragma unroll
        for (int n = 0; n < 32; n++) {
            float y = row[n] + bv;
            S += y; Q = fmaf(y, y, Q);
            dst[n] = y;
        }
        S += __shfl_down_sync(0xffffffffu, S, 1);
        Q += __shfl_down_sync(0xffffffffu, Q, 1);
        if (!half) g_ps[(size_t)cta * C_OUT + o] = make_float2(S, Q);
    }
}

// ---------------- K4: BN finish ---------------------------------
__global__ void bn_finish(const float* __restrict__ gamma, const float* __restrict__ beta) {
    int o = blockIdx.x;
    int t = threadIdx.x;  // 256
    float S = 0.f, Q = 0.f;
    for (int k = t; k < NBLK; k += 256) {
        float2 p = g_ps[(size_t)k * C_OUT + o];
        S += p.x; Q += p.y;
    }
    __shared__ float rs[256], rq[256];
    rs[t] = S; rq[t] = Q;
    __syncthreads();
    for (int st = 128; st > 0; st >>= 1) {
        if (t < st) { rs[t] += rs[t + st]; rq[t] += rq[t + st]; }
        __syncthreads();
    }
    if (t == 0) {
        const float inv_n = 1.f / 65536.f;
        float mean = rs[0] * inv_n;
        float var  = rq[0] * inv_n - mean * mean;
        float r    = rsqrtf(var + 1e-5f);
        float sc   = gamma[o] * r;
        g_scale[o] = sc;
        g_shift[o] = beta[o] - mean * sc;
    }
}

// ---------------- K5: normalize + GELU --------------------------
__device__ __forceinline__ float gelu_f(float x) {
    float z = 0.7978845608028654f * fmaf(0.044715f * x, x * x, x);
    float e = __expf(2.f * z);
    float th = 1.f - __fdividef(2.f, e + 1.f);
    return 0.5f * x * (1.f + th);
}

__global__ void bn_gelu(float* __restrict__ out) {
    int i = blockIdx.x * blockDim.x + threadIdx.x;
    if (i < (BS * C_OUT * 1024) / 4) {
        float4 v = ((const float4*)g_y)[i];
        int o = (i >> 8) & 255;
        float sc = g_scale[o], sh = g_shift[o];
        v.x = gelu_f(fmaf(v.x, sc, sh));
        v.y = gelu_f(fmaf(v.y, sc, sh));
        v.z = gelu_f(fmaf(v.z, sc, sh));
        v.w = gelu_f(fmaf(v.w, sc, sh));
        ((float4*)out)[i] = v;
    }
}

// ---------------- launch ----------------------------------------
extern "C" void kernel_launch(void* const* d_in, const int* in_sizes, int n_in,
                              void* d_out, int out_size) {
    const float* sparse_fea = (const float*)d_in[0];   // [64,256,64]
    const float* dense_fea  = (const float*)d_in[1];   // [64,128,4096]
    const float* stk_coor   = (const float*)d_in[2];   // [64,64,32]
    const float* conv_w     = (const float*)d_in[3];   // [256,128,1,3]
    const float* conv_b     = (const float*)d_in[4];   // [256]
    const float* bn_gamma   = (const float*)d_in[5];   // [256]
    const float* bn_beta    = (const float*)d_in[6];   // [256]

    float* out = (float*)d_out;
    float* sparse_out = out;                            // 524288
    float* dense_out  = out + 524288;                   // 16777216
    float* coor_out   = out + 524288 + 16777216;        // 65536

    cudaFuncSetAttribute(conv_mma_kernel, cudaFuncAttributeMaxDynamicSharedMemorySize, SMEM_TOT);

    fps_kernel<<<BS, N_STK>>>(stk_coor, coor_out);                               // 1
    gather_sparse<<<(BS * SP_EMB * N_HALF + 255) / 256, 256>>>(sparse_fea, sparse_out); // 2
    wsplit<<<(KSTEPS * 8192 + 255) / 256, 256>>>(conv_w);                         // 3
    conv_mma_kernel<<<NBLK, 512, SMEM_TOT>>>(dense_fea, conv_b);                  // 4 (profiled)
    bn_finish<<<C_OUT, 256>>>(bn_gamma, bn_beta);                                 // 5
    bn_gelu<<<(BS * C_OUT * 1024 / 4 + 255) / 256, 256>>>(dense_out);             // 6
}